// round 2
// baseline (speedup 1.0000x reference)
#include <cuda_runtime.h>

#define N_NODES 80000
#define N_EDGES 1280000
#define IN_CH 128
#define HID 64
#define OUT_CH 32

// Scratch (allocation-free rule: __device__ globals). ~52 MB total.
__device__ __align__(256) float g_deg [N_NODES];
__device__ __align__(256) float g_dinv[N_NODES];
__device__ __align__(256) float g_h1  [(size_t)N_NODES * HID];
__device__ __align__(256) float g_out1[(size_t)N_NODES * HID];
__device__ __align__(256) float g_h2  [(size_t)N_NODES * OUT_CH];

__device__ __forceinline__ void red_add_v4(float4* p, float4 v) {
    asm volatile("red.global.add.v4.f32 [%0], {%1, %2, %3, %4};"
                 :: "l"(p), "f"(v.x), "f"(v.y), "f"(v.z), "f"(v.w)
                 : "memory");
}

// ---------------- degree / normalization ----------------

__global__ void k_deg_init() {
    int i = blockIdx.x * blockDim.x + threadIdx.x;
    if (i < N_NODES) g_deg[i] = 1.0f;   // self-loop
}

__global__ void k_deg_count(const int* __restrict__ dst) {
    int e = blockIdx.x * blockDim.x + threadIdx.x;
    if (e < N_EDGES) atomicAdd(&g_deg[dst[e]], 1.0f);
}

__global__ void k_dinv() {
    int i = blockIdx.x * blockDim.x + threadIdx.x;
    if (i < N_NODES) g_dinv[i] = rsqrtf(g_deg[i]);
}

// ---------------- GEMM1: h1 = x @ W1  (128 -> 64) ----------------
// 64 nodes per block, 256 threads: thread = (node, 16 channels).
// K tiled by 32. sX padded to 36 floats/row -> conflict-free.

__global__ void __launch_bounds__(256) k_gemm1(const float* __restrict__ x,
                                               const float* __restrict__ W1) {
    __shared__ float sW[32 * 64];   // [k][c] tile
    __shared__ float sX[64 * 36];   // [node][k] padded
    const int nl = threadIdx.x >> 2;         // 0..63 node-local
    const int cg = (threadIdx.x & 3) << 4;   // channel base: 0,16,32,48
    const int nodeBase = blockIdx.x * 64;

    float acc[16];
#pragma unroll
    for (int i = 0; i < 16; i++) acc[i] = 0.0f;

    for (int kt = 0; kt < IN_CH; kt += 32) {
#pragma unroll
        for (int i = threadIdx.x; i < 32 * 64; i += 256)
            sW[i] = W1[(kt + (i >> 6)) * HID + (i & 63)];
#pragma unroll
        for (int i = threadIdx.x; i < 64 * 32; i += 256) {
            int n = i >> 5, k = i & 31;
            sX[n * 36 + k] = x[(size_t)(nodeBase + n) * IN_CH + kt + k];
        }
        __syncthreads();
#pragma unroll
        for (int k = 0; k < 32; ++k) {
            float xv = sX[nl * 36 + k];
            const float4* w4 = (const float4*)(sW + k * 64 + cg);
            float4 w0 = w4[0], w1 = w4[1], w2 = w4[2], w3 = w4[3];
            acc[0]  += xv * w0.x;  acc[1]  += xv * w0.y;
            acc[2]  += xv * w0.z;  acc[3]  += xv * w0.w;
            acc[4]  += xv * w1.x;  acc[5]  += xv * w1.y;
            acc[6]  += xv * w1.z;  acc[7]  += xv * w1.w;
            acc[8]  += xv * w2.x;  acc[9]  += xv * w2.y;
            acc[10] += xv * w2.z;  acc[11] += xv * w2.w;
            acc[12] += xv * w3.x;  acc[13] += xv * w3.y;
            acc[14] += xv * w3.z;  acc[15] += xv * w3.w;
        }
        __syncthreads();
    }
    float4* out = (float4*)(g_h1 + (size_t)(nodeBase + nl) * HID + cg);
    out[0] = make_float4(acc[0],  acc[1],  acc[2],  acc[3]);
    out[1] = make_float4(acc[4],  acc[5],  acc[6],  acc[7]);
    out[2] = make_float4(acc[8],  acc[9],  acc[10], acc[11]);
    out[3] = make_float4(acc[12], acc[13], acc[14], acc[15]);
}

// ---------------- self-loop + bias init (overwrites -> replay-safe) ----------------

__global__ void k_self1(const float* __restrict__ b1) {
    int t = blockIdx.x * blockDim.x + threadIdx.x;   // over N*16 float4 chunks
    if (t >= N_NODES * 16) return;
    int n = t >> 4, q = t & 15;
    float s = g_dinv[n]; s = s * s;
    float4 hv = ((const float4*)g_h1)[(size_t)n * 16 + q];
    float4 bv = ((const float4*)b1)[q];
    ((float4*)g_out1)[(size_t)n * 16 + q] =
        make_float4(bv.x + s * hv.x, bv.y + s * hv.y,
                    bv.z + s * hv.z, bv.w + s * hv.w);
}

// ---------------- edge scatter layer 1 (64 ch = 16 float4 per edge) ----------------

__global__ void k_scatter1(const int* __restrict__ src,
                           const int* __restrict__ dst) {
    int t = blockIdx.x * blockDim.x + threadIdx.x;
    int e = t >> 4, q = t & 15;
    if (e >= N_EDGES) return;
    int s = src[e], d = dst[e];
    float nrm = g_dinv[s] * g_dinv[d];
    float4 v = ((const float4*)g_h1)[(size_t)s * 16 + q];
    v.x *= nrm; v.y *= nrm; v.z *= nrm; v.w *= nrm;
    red_add_v4(((float4*)g_out1) + (size_t)d * 16 + q, v);
}

// ---------------- GEMM2: h2 = relu(out1) @ W2  (64 -> 32) ----------------

__global__ void __launch_bounds__(256) k_gemm2(const float* __restrict__ W2) {
    __shared__ float sW[64 * 32];   // full W2, 8 KB
    __shared__ float sX[64 * 68];   // 64 nodes x 64 (padded)
    const int nl = threadIdx.x >> 2;
    const int cg = (threadIdx.x & 3) << 3;   // 0,8,16,24
    const int nodeBase = blockIdx.x * 64;

    for (int i = threadIdx.x; i < 64 * 32; i += 256)
        sW[i] = W2[i];
    for (int i = threadIdx.x; i < 64 * 64; i += 256) {
        int n = i >> 6, k = i & 63;
        sX[n * 68 + k] = fmaxf(g_out1[(size_t)(nodeBase + n) * HID + k], 0.0f);
    }
    __syncthreads();

    float acc[8];
#pragma unroll
    for (int i = 0; i < 8; i++) acc[i] = 0.0f;
#pragma unroll 8
    for (int k = 0; k < HID; ++k) {
        float xv = sX[nl * 68 + k];
        const float4* w4 = (const float4*)(sW + k * 32 + cg);
        float4 w0 = w4[0], w1 = w4[1];
        acc[0] += xv * w0.x; acc[1] += xv * w0.y;
        acc[2] += xv * w0.z; acc[3] += xv * w0.w;
        acc[4] += xv * w1.x; acc[5] += xv * w1.y;
        acc[6] += xv * w1.z; acc[7] += xv * w1.w;
    }
    float4* out = (float4*)(g_h2 + (size_t)(nodeBase + nl) * OUT_CH + cg);
    out[0] = make_float4(acc[0], acc[1], acc[2], acc[3]);
    out[1] = make_float4(acc[4], acc[5], acc[6], acc[7]);
}

__global__ void k_self2(const float* __restrict__ b2, float* __restrict__ out) {
    int t = blockIdx.x * blockDim.x + threadIdx.x;   // over N*8
    if (t >= N_NODES * 8) return;
    int n = t >> 3, q = t & 7;
    float s = g_dinv[n]; s = s * s;
    float4 hv = ((const float4*)g_h2)[(size_t)n * 8 + q];
    float4 bv = ((const float4*)b2)[q];
    ((float4*)out)[(size_t)n * 8 + q] =
        make_float4(bv.x + s * hv.x, bv.y + s * hv.y,
                    bv.z + s * hv.z, bv.w + s * hv.w);
}

__global__ void k_scatter2(const int* __restrict__ src,
                           const int* __restrict__ dst,
                           float* __restrict__ out) {
    int t = blockIdx.x * blockDim.x + threadIdx.x;
    int e = t >> 3, q = t & 7;
    if (e >= N_EDGES) return;
    int s = src[e], d = dst[e];
    float nrm = g_dinv[s] * g_dinv[d];
    float4 v = ((const float4*)g_h2)[(size_t)s * 8 + q];
    v.x *= nrm; v.y *= nrm; v.z *= nrm; v.w *= nrm;
    red_add_v4(((float4*)out) + (size_t)d * 8 + q, v);
}

// ---------------- launch ----------------

extern "C" void kernel_launch(void* const* d_in, const int* in_sizes, int n_in,
                              void* d_out, int out_size) {
    const float* x   = (const float*)d_in[0];
    const int*   ei  = (const int*)d_in[1];   // int32: JAX x64-disabled downcast
    const float* W1  = (const float*)d_in[2];
    const float* b1  = (const float*)d_in[3];
    const float* W2  = (const float*)d_in[4];
    const float* b2  = (const float*)d_in[5];
    float*       out = (float*)d_out;

    const int* src = ei;
    const int* dst = ei + N_EDGES;

    k_deg_init <<<(N_NODES + 255) / 256, 256>>>();
    k_deg_count<<<(N_EDGES + 255) / 256, 256>>>(dst);
    k_dinv     <<<(N_NODES + 255) / 256, 256>>>();

    k_gemm1    <<<N_NODES / 64, 256>>>(x, W1);
    k_self1    <<<(N_NODES * 16 + 255) / 256, 256>>>(b1);
    k_scatter1 <<<(N_EDGES * 16 + 255) / 256, 256>>>(src, dst);

    k_gemm2    <<<N_NODES / 64, 256>>>(W2);
    k_self2    <<<(N_NODES * 8 + 255) / 256, 256>>>(b2, out);
    k_scatter2 <<<(N_EDGES * 8 + 255) / 256, 256>>>(src, dst, out);
}

// round 3
// speedup vs baseline: 1.5948x; 1.5948x over previous
#include <cuda_runtime.h>

#define N_NODES 80000
#define N_EDGES 1280000
#define IN_CH 128
#define HID 64
#define OUT_CH 32

__device__ __align__(256) float g_deg [N_NODES];
__device__ __align__(256) float g_dinv[N_NODES];
__device__ __align__(256) float g_h1  [(size_t)N_NODES * HID];
__device__ __align__(256) float g_out1[(size_t)N_NODES * HID];
__device__ __align__(256) float g_h2  [(size_t)N_NODES * OUT_CH];

__device__ __forceinline__ void red_add_v4(float4* p, float4 v) {
    asm volatile("red.global.add.v4.f32 [%0], {%1, %2, %3, %4};"
                 :: "l"(p), "f"(v.x), "f"(v.y), "f"(v.z), "f"(v.w)
                 : "memory");
}

// ---------------- degree / normalization ----------------

__global__ void k_deg_init() {
    int i = blockIdx.x * blockDim.x + threadIdx.x;
    if (i < N_NODES) g_deg[i] = 1.0f;   // self-loop
}

__global__ void k_deg_count(const int* __restrict__ dst) {
    int e = blockIdx.x * blockDim.x + threadIdx.x;
    if (e < N_EDGES) atomicAdd(&g_deg[dst[e]], 1.0f);
}

__global__ void k_dinv() {
    int i = blockIdx.x * blockDim.x + threadIdx.x;
    if (i < N_NODES) g_dinv[i] = rsqrtf(g_deg[i]);
}

// ---------------- GEMM1: h1 = x @ W1 (128 -> 64) ----------------
// 128 threads/block, tile 128 nodes x 64 ch, K-tile 32.
// Thread = 4 nodes x 16 channels (64 acc). Per k: 4 scalar LDS + 4 LDS.128
// for 64 FMA -> FMA-pipe bound.

__global__ void __launch_bounds__(128) k_gemm1(const float* __restrict__ x,
                                               const float* __restrict__ W1) {
    __shared__ float sW[32 * 64];    // [k][c]
    __shared__ float sX[128 * 33];   // [node][k] pad 33 -> conflict-free
    const int tn = threadIdx.x & 3;
    const int tm = threadIdx.x >> 2;          // 0..31
    const int cg = tn << 4;                   // 0,16,32,48
    const int nodeBase = blockIdx.x * 128;

    float acc[4][16];
#pragma unroll
    for (int j = 0; j < 4; j++)
#pragma unroll
        for (int c = 0; c < 16; c++) acc[j][c] = 0.0f;

    for (int kt = 0; kt < IN_CH; kt += 32) {
        // W tile: 32x64 floats = 512 float4
#pragma unroll
        for (int i = threadIdx.x; i < 512; i += 128)
            ((float4*)sW)[i] =
                ((const float4*)W1)[(size_t)(kt + (i >> 4)) * 16 + (i & 15)];
        // X tile: 128x32 floats = 1024 float4, transposed scalar stores
#pragma unroll
        for (int i = threadIdx.x; i < 1024; i += 128) {
            int n = i >> 3, f4 = i & 7;
            float4 v = ((const float4*)x)[(size_t)(nodeBase + n) * 32 + (kt >> 2) + f4];
            float* p = sX + n * 33 + (f4 << 2);
            p[0] = v.x; p[1] = v.y; p[2] = v.z; p[3] = v.w;
        }
        __syncthreads();
#pragma unroll 2
        for (int k = 0; k < 32; ++k) {
            const float4* w4 = (const float4*)(sW + k * 64 + cg);
            float4 w0 = w4[0], w1 = w4[1], w2 = w4[2], w3 = w4[3];
            float xv[4];
#pragma unroll
            for (int j = 0; j < 4; j++) xv[j] = sX[(tm * 4 + j) * 33 + k];
#pragma unroll
            for (int j = 0; j < 4; j++) {
                acc[j][0]  += xv[j] * w0.x;  acc[j][1]  += xv[j] * w0.y;
                acc[j][2]  += xv[j] * w0.z;  acc[j][3]  += xv[j] * w0.w;
                acc[j][4]  += xv[j] * w1.x;  acc[j][5]  += xv[j] * w1.y;
                acc[j][6]  += xv[j] * w1.z;  acc[j][7]  += xv[j] * w1.w;
                acc[j][8]  += xv[j] * w2.x;  acc[j][9]  += xv[j] * w2.y;
                acc[j][10] += xv[j] * w2.z;  acc[j][11] += xv[j] * w2.w;
                acc[j][12] += xv[j] * w3.x;  acc[j][13] += xv[j] * w3.y;
                acc[j][14] += xv[j] * w3.z;  acc[j][15] += xv[j] * w3.w;
            }
        }
        __syncthreads();
    }
#pragma unroll
    for (int j = 0; j < 4; j++) {
        float4* out = (float4*)(g_h1 + (size_t)(nodeBase + tm * 4 + j) * HID + cg);
        out[0] = make_float4(acc[j][0],  acc[j][1],  acc[j][2],  acc[j][3]);
        out[1] = make_float4(acc[j][4],  acc[j][5],  acc[j][6],  acc[j][7]);
        out[2] = make_float4(acc[j][8],  acc[j][9],  acc[j][10], acc[j][11]);
        out[3] = make_float4(acc[j][12], acc[j][13], acc[j][14], acc[j][15]);
    }
}

// ---------------- self-loop + bias init (overwrite -> replay-safe) ----------------

__global__ void k_self1(const float* __restrict__ b1) {
    int t = blockIdx.x * blockDim.x + threadIdx.x;
    if (t >= N_NODES * 16) return;
    int n = t >> 4, q = t & 15;
    float s = g_dinv[n]; s = s * s;
    float4 hv = ((const float4*)g_h1)[(size_t)n * 16 + q];
    float4 bv = ((const float4*)b1)[q];
    ((float4*)g_out1)[(size_t)n * 16 + q] =
        make_float4(bv.x + s * hv.x, bv.y + s * hv.y,
                    bv.z + s * hv.z, bv.w + s * hv.w);
}

// ---------------- edge scatter layer 1 ----------------

__global__ void k_scatter1(const int* __restrict__ src,
                           const int* __restrict__ dst) {
    int t = blockIdx.x * blockDim.x + threadIdx.x;
    int e = t >> 4, q = t & 15;
    if (e >= N_EDGES) return;
    int s = src[e], d = dst[e];
    float nrm = g_dinv[s] * g_dinv[d];
    float4 v = ((const float4*)g_h1)[(size_t)s * 16 + q];
    v.x *= nrm; v.y *= nrm; v.z *= nrm; v.w *= nrm;
    red_add_v4(((float4*)g_out1) + (size_t)d * 16 + q, v);
}

// ---------------- GEMM2: h2 = relu(out1) @ W2 (64 -> 32) ----------------
// 128 threads/block, tile 128 nodes x 32 ch, full K=64 in smem.
// Thread = 4 nodes x 8 channels (32 acc). Per k: 4 scalar LDS + 2 LDS.128
// for 32 FMA.

__global__ void __launch_bounds__(128) k_gemm2(const float* __restrict__ W2) {
    __shared__ float sW[64 * 32];    // 8 KB
    __shared__ float sX[128 * 65];   // pad 65 -> conflict-free reads
    const int tn = threadIdx.x & 3;
    const int tm = threadIdx.x >> 2;
    const int cg = tn << 3;          // 0,8,16,24
    const int nodeBase = blockIdx.x * 128;

#pragma unroll
    for (int i = threadIdx.x; i < 512; i += 128)
        ((float4*)sW)[i] = ((const float4*)W2)[i];
#pragma unroll
    for (int i = threadIdx.x; i < 2048; i += 128) {
        int n = i >> 4, f4 = i & 15;
        float4 v = ((const float4*)g_out1)[(size_t)(nodeBase + n) * 16 + f4];
        float* p = sX + n * 65 + (f4 << 2);
        p[0] = fmaxf(v.x, 0.0f); p[1] = fmaxf(v.y, 0.0f);
        p[2] = fmaxf(v.z, 0.0f); p[3] = fmaxf(v.w, 0.0f);
    }
    __syncthreads();

    float acc[4][8];
#pragma unroll
    for (int j = 0; j < 4; j++)
#pragma unroll
        for (int c = 0; c < 8; c++) acc[j][c] = 0.0f;

#pragma unroll 4
    for (int k = 0; k < HID; ++k) {
        const float4* w4 = (const float4*)(sW + k * 32 + cg);
        float4 w0 = w4[0], w1 = w4[1];
        float xv[4];
#pragma unroll
        for (int j = 0; j < 4; j++) xv[j] = sX[(tm * 4 + j) * 65 + k];
#pragma unroll
        for (int j = 0; j < 4; j++) {
            acc[j][0] += xv[j] * w0.x; acc[j][1] += xv[j] * w0.y;
            acc[j][2] += xv[j] * w0.z; acc[j][3] += xv[j] * w0.w;
            acc[j][4] += xv[j] * w1.x; acc[j][5] += xv[j] * w1.y;
            acc[j][6] += xv[j] * w1.z; acc[j][7] += xv[j] * w1.w;
        }
    }
#pragma unroll
    for (int j = 0; j < 4; j++) {
        float4* out = (float4*)(g_h2 + (size_t)(nodeBase + tm * 4 + j) * OUT_CH + cg);
        out[0] = make_float4(acc[j][0], acc[j][1], acc[j][2], acc[j][3]);
        out[1] = make_float4(acc[j][4], acc[j][5], acc[j][6], acc[j][7]);
    }
}

__global__ void k_self2(const float* __restrict__ b2, float* __restrict__ out) {
    int t = blockIdx.x * blockDim.x + threadIdx.x;
    if (t >= N_NODES * 8) return;
    int n = t >> 3, q = t & 7;
    float s = g_dinv[n]; s = s * s;
    float4 hv = ((const float4*)g_h2)[(size_t)n * 8 + q];
    float4 bv = ((const float4*)b2)[q];
    ((float4*)out)[(size_t)n * 8 + q] =
        make_float4(bv.x + s * hv.x, bv.y + s * hv.y,
                    bv.z + s * hv.z, bv.w + s * hv.w);
}

__global__ void k_scatter2(const int* __restrict__ src,
                           const int* __restrict__ dst,
                           float* __restrict__ out) {
    int t = blockIdx.x * blockDim.x + threadIdx.x;
    int e = t >> 3, q = t & 7;
    if (e >= N_EDGES) return;
    int s = src[e], d = dst[e];
    float nrm = g_dinv[s] * g_dinv[d];
    float4 v = ((const float4*)g_h2)[(size_t)s * 8 + q];
    v.x *= nrm; v.y *= nrm; v.z *= nrm; v.w *= nrm;
    red_add_v4(((float4*)out) + (size_t)d * 8 + q, v);
}

// ---------------- launch ----------------

extern "C" void kernel_launch(void* const* d_in, const int* in_sizes, int n_in,
                              void* d_out, int out_size) {
    const float* x   = (const float*)d_in[0];
    const int*   ei  = (const int*)d_in[1];   // int32 (JAX x64 disabled)
    const float* W1  = (const float*)d_in[2];
    const float* b1  = (const float*)d_in[3];
    const float* W2  = (const float*)d_in[4];
    const float* b2  = (const float*)d_in[5];
    float*       out = (float*)d_out;

    const int* src = ei;
    const int* dst = ei + N_EDGES;

    k_deg_init <<<(N_NODES + 255) / 256, 256>>>();
    k_deg_count<<<(N_EDGES + 255) / 256, 256>>>(dst);
    k_dinv     <<<(N_NODES + 255) / 256, 256>>>();

    k_gemm1    <<<N_NODES / 128, 128>>>(x, W1);
    k_self1    <<<(N_NODES * 16 + 255) / 256, 256>>>(b1);
    k_scatter1 <<<(N_EDGES * 16 + 255) / 256, 256>>>(src, dst);

    k_gemm2    <<<N_NODES / 128, 128>>>(W2);
    k_self2    <<<(N_NODES * 8 + 255) / 256, 256>>>(b2, out);
    k_scatter2 <<<(N_EDGES * 8 + 255) / 256, 256>>>(src, dst, out);
}

// round 4
// speedup vs baseline: 1.9214x; 1.2048x over previous
#include <cuda_runtime.h>

#define N_NODES 80000
#define N_EDGES 1280000
#define IN_CH 128
#define HID 64
#define OUT_CH 32

#define SCAN_BLK 512
#define N_SCAN_BLOCKS ((N_NODES + SCAN_BLK - 1) / SCAN_BLK)   // 157

// Scratch (__device__ globals; no allocation allowed)
__device__ __align__(256) float g_dinv[N_NODES];
__device__ __align__(256) int   g_cnt [N_NODES];
__device__ __align__(256) int   g_offs[N_NODES + 1];
__device__ __align__(256) int   g_cursor[N_NODES];
__device__ __align__(256) int   g_bsum[N_SCAN_BLOCKS];
__device__ __align__(256) int   g_csr [N_EDGES];
__device__ __align__(256) float g_h1s [(size_t)N_NODES * HID];     // dinv * (x@W1)
__device__ __align__(256) float g_out1[(size_t)N_NODES * HID];     // relu(b1 + dinv*(...))
__device__ __align__(256) float g_h2s [(size_t)N_NODES * OUT_CH];  // dinv * (out1@W2)

// ---------------- degree counting / CSR build ----------------

__global__ void k_zero_cnt() {
    int i = blockIdx.x * blockDim.x + threadIdx.x;
    if (i < N_NODES) g_cnt[i] = 0;
}

__global__ void k_cnt(const int* __restrict__ dst) {
    int e = blockIdx.x * blockDim.x + threadIdx.x;
    if (e < N_EDGES) atomicAdd(&g_cnt[dst[e]], 1);
}

__global__ void k_dinv() {
    int i = blockIdx.x * blockDim.x + threadIdx.x;
    if (i < N_NODES) g_dinv[i] = rsqrtf((float)(g_cnt[i] + 1));  // + self loop
}

// scan1: per-block inclusive scan of counts (512/block); emit exclusive-local + block sum
__global__ void __launch_bounds__(SCAN_BLK) k_scan1() {
    __shared__ int s[2 * SCAN_BLK];
    int t = threadIdx.x;
    int gi = blockIdx.x * SCAN_BLK + t;
    int v = (gi < N_NODES) ? g_cnt[gi] : 0;
    int* a = s; int* b = s + SCAN_BLK;
    a[t] = v;
    __syncthreads();
#pragma unroll
    for (int off = 1; off < SCAN_BLK; off <<= 1) {
        b[t] = a[t] + ((t >= off) ? a[t - off] : 0);
        int* tmp = a; a = b; b = tmp;
        __syncthreads();
    }
    if (gi < N_NODES) g_offs[gi] = a[t] - v;   // exclusive, block-local
    if (t == SCAN_BLK - 1) g_bsum[blockIdx.x] = a[t];
}

// scan2: serial scan of 157 block sums (single thread; trivial)
__global__ void k_scan2() {
    if (threadIdx.x == 0 && blockIdx.x == 0) {
        int run = 0;
        for (int i = 0; i < N_SCAN_BLOCKS; i++) {
            int v = g_bsum[i];
            g_bsum[i] = run;
            run += v;
        }
        g_offs[N_NODES] = N_EDGES;
    }
}

// scan3: add block offsets; init cursor
__global__ void k_scan3() {
    int gi = blockIdx.x * blockDim.x + threadIdx.x;
    if (gi < N_NODES) {
        int o = g_offs[gi] + g_bsum[gi / SCAN_BLK];
        g_offs[gi] = o;
        g_cursor[gi] = o;
    }
}

__global__ void k_fill(const int* __restrict__ src, const int* __restrict__ dst) {
    int e = blockIdx.x * blockDim.x + threadIdx.x;
    if (e < N_EDGES) {
        int pos = atomicAdd(&g_cursor[dst[e]], 1);
        g_csr[pos] = src[e];
    }
}

// ---------------- GEMM1: h1s = dinv * (x @ W1) (128 -> 64) ----------------
// 128 threads/block, tile 128 nodes x 64 ch, K-tile 32.
// Thread = 4 nodes x 16 channels (64 acc).

__global__ void __launch_bounds__(128) k_gemm1(const float* __restrict__ x,
                                               const float* __restrict__ W1) {
    __shared__ float sW[32 * 64];
    __shared__ float sX[128 * 33];
    const int tn = threadIdx.x & 3;
    const int tm = threadIdx.x >> 2;
    const int cg = tn << 4;
    const int nodeBase = blockIdx.x * 128;

    float acc[4][16];
#pragma unroll
    for (int j = 0; j < 4; j++)
#pragma unroll
        for (int c = 0; c < 16; c++) acc[j][c] = 0.0f;

    for (int kt = 0; kt < IN_CH; kt += 32) {
#pragma unroll
        for (int i = threadIdx.x; i < 512; i += 128)
            ((float4*)sW)[i] =
                ((const float4*)W1)[(size_t)(kt + (i >> 4)) * 16 + (i & 15)];
#pragma unroll
        for (int i = threadIdx.x; i < 1024; i += 128) {
            int n = i >> 3, f4 = i & 7;
            float4 v = ((const float4*)x)[(size_t)(nodeBase + n) * 32 + (kt >> 2) + f4];
            float* p = sX + n * 33 + (f4 << 2);
            p[0] = v.x; p[1] = v.y; p[2] = v.z; p[3] = v.w;
        }
        __syncthreads();
#pragma unroll 2
        for (int k = 0; k < 32; ++k) {
            const float4* w4 = (const float4*)(sW + k * 64 + cg);
            float4 w0 = w4[0], w1 = w4[1], w2 = w4[2], w3 = w4[3];
            float xv[4];
#pragma unroll
            for (int j = 0; j < 4; j++) xv[j] = sX[(tm * 4 + j) * 33 + k];
#pragma unroll
            for (int j = 0; j < 4; j++) {
                acc[j][0]  += xv[j] * w0.x;  acc[j][1]  += xv[j] * w0.y;
                acc[j][2]  += xv[j] * w0.z;  acc[j][3]  += xv[j] * w0.w;
                acc[j][4]  += xv[j] * w1.x;  acc[j][5]  += xv[j] * w1.y;
                acc[j][6]  += xv[j] * w1.z;  acc[j][7]  += xv[j] * w1.w;
                acc[j][8]  += xv[j] * w2.x;  acc[j][9]  += xv[j] * w2.y;
                acc[j][10] += xv[j] * w2.z;  acc[j][11] += xv[j] * w2.w;
                acc[j][12] += xv[j] * w3.x;  acc[j][13] += xv[j] * w3.y;
                acc[j][14] += xv[j] * w3.z;  acc[j][15] += xv[j] * w3.w;
            }
        }
        __syncthreads();
    }
#pragma unroll
    for (int j = 0; j < 4; j++) {
        int node = nodeBase + tm * 4 + j;
        float dj = g_dinv[node];
        float4* out = (float4*)(g_h1s + (size_t)node * HID + cg);
#pragma unroll
        for (int q = 0; q < 4; q++)
            out[q] = make_float4(dj * acc[j][4 * q], dj * acc[j][4 * q + 1],
                                 dj * acc[j][4 * q + 2], dj * acc[j][4 * q + 3]);
    }
}

// ---------------- aggregation layer 1 (warp per node, lane = 2 channels) ----------------
// out1[i] = relu(b1 + dinv[i] * (h1s[i] + sum_{j->i} h1s[j]))

__global__ void __launch_bounds__(256) k_agg1(const float* __restrict__ b1) {
    int node = blockIdx.x * 8 + (threadIdx.x >> 5);
    if (node >= N_NODES) return;
    int lane = threadIdx.x & 31;
    const float2* h = (const float2*)g_h1s;
    int beg = g_offs[node], end = g_offs[node + 1];
    float2 acc = h[(size_t)node * 32 + lane];   // self
    for (int c = beg; c < end; c += 32) {
        int idx = (c + lane < end) ? g_csr[c + lane] : 0;
        int m = min(32, end - c);
        for (int t = 0; t < m; ++t) {
            int j = __shfl_sync(0xffffffffu, idx, t);
            float2 v = h[(size_t)j * 32 + lane];
            acc.x += v.x; acc.y += v.y;
        }
    }
    float di = g_dinv[node];
    float2 bv = ((const float2*)b1)[lane];
    float2 o = make_float2(fmaxf(bv.x + di * acc.x, 0.0f),
                           fmaxf(bv.y + di * acc.y, 0.0f));
    ((float2*)g_out1)[(size_t)node * 32 + lane] = o;
}

// ---------------- GEMM2: h2s = dinv * (out1 @ W2) (64 -> 32) ----------------

__global__ void __launch_bounds__(128) k_gemm2(const float* __restrict__ W2) {
    __shared__ float sW[64 * 32];
    __shared__ float sX[128 * 65];
    const int tn = threadIdx.x & 3;
    const int tm = threadIdx.x >> 2;
    const int cg = tn << 3;
    const int nodeBase = blockIdx.x * 128;

#pragma unroll
    for (int i = threadIdx.x; i < 512; i += 128)
        ((float4*)sW)[i] = ((const float4*)W2)[i];
#pragma unroll
    for (int i = threadIdx.x; i < 2048; i += 128) {
        int n = i >> 4, f4 = i & 15;
        float4 v = ((const float4*)g_out1)[(size_t)(nodeBase + n) * 16 + f4];
        float* p = sX + n * 65 + (f4 << 2);
        p[0] = v.x; p[1] = v.y; p[2] = v.z; p[3] = v.w;   // relu already applied
    }
    __syncthreads();

    float acc[4][8];
#pragma unroll
    for (int j = 0; j < 4; j++)
#pragma unroll
        for (int c = 0; c < 8; c++) acc[j][c] = 0.0f;

#pragma unroll 4
    for (int k = 0; k < HID; ++k) {
        const float4* w4 = (const float4*)(sW + k * 32 + cg);
        float4 w0 = w4[0], w1 = w4[1];
        float xv[4];
#pragma unroll
        for (int j = 0; j < 4; j++) xv[j] = sX[(tm * 4 + j) * 65 + k];
#pragma unroll
        for (int j = 0; j < 4; j++) {
            acc[j][0] += xv[j] * w0.x; acc[j][1] += xv[j] * w0.y;
            acc[j][2] += xv[j] * w0.z; acc[j][3] += xv[j] * w0.w;
            acc[j][4] += xv[j] * w1.x; acc[j][5] += xv[j] * w1.y;
            acc[j][6] += xv[j] * w1.z; acc[j][7] += xv[j] * w1.w;
        }
    }
#pragma unroll
    for (int j = 0; j < 4; j++) {
        int node = nodeBase + tm * 4 + j;
        float dj = g_dinv[node];
        float4* out = (float4*)(g_h2s + (size_t)node * OUT_CH + cg);
        out[0] = make_float4(dj * acc[j][0], dj * acc[j][1],
                             dj * acc[j][2], dj * acc[j][3]);
        out[1] = make_float4(dj * acc[j][4], dj * acc[j][5],
                             dj * acc[j][6], dj * acc[j][7]);
    }
}

// ---------------- aggregation layer 2 (warp per node, lane = 1 channel) ----------------

__global__ void __launch_bounds__(256) k_agg2(const float* __restrict__ b2,
                                              float* __restrict__ out) {
    int node = blockIdx.x * 8 + (threadIdx.x >> 5);
    if (node >= N_NODES) return;
    int lane = threadIdx.x & 31;
    int beg = g_offs[node], end = g_offs[node + 1];
    float acc = g_h2s[(size_t)node * 32 + lane];   // self
    for (int c = beg; c < end; c += 32) {
        int idx = (c + lane < end) ? g_csr[c + lane] : 0;
        int m = min(32, end - c);
        for (int t = 0; t < m; ++t) {
            int j = __shfl_sync(0xffffffffu, idx, t);
            acc += g_h2s[(size_t)j * 32 + lane];
        }
    }
    float di = g_dinv[node];
    out[(size_t)node * 32 + lane] = b2[lane] + di * acc;
}

// ---------------- launch ----------------

extern "C" void kernel_launch(void* const* d_in, const int* in_sizes, int n_in,
                              void* d_out, int out_size) {
    const float* x   = (const float*)d_in[0];
    const int*   ei  = (const int*)d_in[1];   // int32 (JAX x64 disabled)
    const float* W1  = (const float*)d_in[2];
    const float* b1  = (const float*)d_in[3];
    const float* W2  = (const float*)d_in[4];
    const float* b2  = (const float*)d_in[5];
    float*       out = (float*)d_out;

    const int* src = ei;
    const int* dst = ei + N_EDGES;

    k_zero_cnt<<<(N_NODES + 255) / 256, 256>>>();
    k_cnt     <<<(N_EDGES + 255) / 256, 256>>>(dst);
    k_dinv    <<<(N_NODES + 255) / 256, 256>>>();
    k_scan1   <<<N_SCAN_BLOCKS, SCAN_BLK>>>();
    k_scan2   <<<1, 32>>>();
    k_scan3   <<<(N_NODES + 255) / 256, 256>>>();
    k_fill    <<<(N_EDGES + 255) / 256, 256>>>(src, dst);

    k_gemm1   <<<N_NODES / 128, 128>>>(x, W1);
    k_agg1    <<<(N_NODES + 7) / 8, 256>>>(b1);
    k_gemm2   <<<N_NODES / 128, 128>>>(W2);
    k_agg2    <<<(N_NODES + 7) / 8, 256>>>(b2, out);
}